// round 10
// baseline (speedup 1.0000x reference)
#include <cuda_runtime.h>
#include <cuda_fp16.h>

#define Bb 1024
#define Ss 128
#define Nn 256
#define Mm 32
#define NU 6
#define GRID 296           // single wave at occ 2; pairs (b, b+148) co-locate
#define REC_CAP 96
#define SEN_CAP 56

typedef unsigned long long ull;

// Compacted per-column pair tables, indexed by SLOT (count-sorted lane).
__device__ float4   g_recA[REC_CAP * Nn];
__device__ float4   g_recB[REC_CAP * Nn];
__device__ unsigned g_recIdx[REC_CAP * Nn];
__device__ float4   g_senA[SEN_CAP * Nn];
__device__ float4   g_senB[SEN_CAP * Nn];
__device__ unsigned g_senIdx[SEN_CAP * Nn];
__device__ int      g_recCnt[Nn], g_senCnt[Nn];   // per SLOT (padded pair count)
__device__ float    g_ncoT[2][Nn], g_dcoT[2][Nn]; // per SLOT
__device__ int      g_perm[Nn];                   // slot -> column
__device__ int      g_rank[Nn];                   // column -> slot
__device__ int      g_cnt0[Nn];                   // per-column recurrent nonzero count

__device__ __forceinline__ __half2 fast_tanh_h2(__half2 x) {
    unsigned r, a = *reinterpret_cast<unsigned*>(&x);
    asm("tanh.approx.f16x2 %0, %1;" : "=r"(r) : "r"(a));
    return *reinterpret_cast<__half2*>(&r);
}
__device__ __forceinline__ ull pk2(float lo, float hi) {
    ull r; asm("mov.b64 %0, {%1, %2};" : "=l"(r) : "f"(lo), "f"(hi)); return r;
}
__device__ __forceinline__ float2 unpk2(ull a) {
    float lo, hi; asm("mov.b64 {%0, %1}, %2;" : "=f"(lo), "=f"(hi) : "l"(a));
    return make_float2(lo, hi);
}
__device__ __forceinline__ ull fma2(ull a, ull b, ull c) {
    ull d; asm("fma.rn.f32x2 %0, %1, %2, %3;" : "=l"(d) : "l"(a), "l"(b), "l"(c));
    return d;
}

// ---------------------------------------------------------------------------
// P-count: per-column recurrent nonzero count (256 blocks, parallel)
// ---------------------------------------------------------------------------
__global__ void pack_count(const float* __restrict__ mask) {
    __shared__ int red[Nn];
    const int n = blockIdx.x, i = threadIdx.x;
    red[i] = (mask[i * Nn + n] != 0.f) ? 1 : 0;
    __syncthreads();
#pragma unroll
    for (int s = Nn / 2; s > 0; s >>= 1) {
        if (i < s) red[i] += red[i + s];
        __syncthreads();
    }
    if (i == 0) g_cnt0[n] = red[0];
}

// ---------------------------------------------------------------------------
// P-rank: rank columns (count desc, tie index asc) -> perm/rank. 1 block.
// ---------------------------------------------------------------------------
__global__ void pack_rank() {
    __shared__ int cnt[Nn];
    const int n = threadIdx.x;
    cnt[n] = g_cnt0[n];
    __syncthreads();
    const int c = cnt[n];
    int rank = 0;
    for (int m = 0; m < Nn; m++) {
        int cm = cnt[m];
        if (cm > c || (cm == c && m < n)) rank++;
    }
    g_rank[n] = rank;
    g_perm[rank] = n;
}

// ---------------------------------------------------------------------------
// P1: one block per column; compact nonzeros into slot-indexed tables.
// Residue buckets by i&7 rotated by slot&7, ascending i within bucket.
// ---------------------------------------------------------------------------
__global__ void pack_phase1(const float* __restrict__ sigma, const float* __restrict__ mu,
                            const float* __restrict__ w,     const float* __restrict__ erev,
                            const float* __restrict__ mask,
                            const float* __restrict__ ssigma, const float* __restrict__ smu,
                            const float* __restrict__ sw,     const float* __restrict__ serev,
                            const float* __restrict__ smask) {
    const int n   = blockIdx.x;
    const bool rc = (blockIdx.y == 0);
    const int D   = rc ? Nn : Ss;
    const int cap = rc ? REC_CAP : SEN_CAP;
    const int i   = threadIdx.x;
    const int slot = g_rank[n];

    float4*   TA = rc ? g_recA : g_senA;
    float4*   TBt = rc ? g_recB : g_senB;
    unsigned* TI = rc ? g_recIdx : g_senIdx;

    __shared__ int hist[8];
    __shared__ unsigned char flag[Nn];
    __shared__ float redZ[Nn], redW[Nn];

    if (i < 8) hist[i] = 0;
    float mv = 0.f, sgv = 0.f, muv = 0.f, wv = 0.f, ev = 0.f;
    if (i < D) {
        if (rc) {
            mv = mask[i * Nn + n];  sgv = sigma[i * Nn + n];  muv = mu[i * Nn + n];
            wv = w[i * Nn + n];     ev  = erev[i * Nn + n];
        } else {
            mv = smask[i * Nn + n]; sgv = ssigma[i * Nn + n]; muv = smu[i * Nn + n];
            wv = sw[i * Nn + n];    ev  = serev[i * Nn + n];
        }
    }
    const bool nz = (i < D) && (mv != 0.f);
    flag[i] = nz ? 1 : 0;
    __syncthreads();
    if (nz) atomicAdd(&hist[i & 7], 1);
    __syncthreads();

    float px = 0.5f * sgv;
    float py = -px * muv;
    float pw = 0.5f * wv;
    float pz = pw * ev;

    if (nz) {
        const int r0 = slot & 7;
        const int myPr = ((i & 7) - r0) & 7;
        int start = 0;
#pragma unroll
        for (int b = 0; b < 8; b++)
            if ((((b - r0) & 7)) < myPr) start += hist[b];
        int rank = 0;
        for (int j = (i & 7); j < i; j += 8) rank += flag[j];
        int sl = start + rank;
        int p = sl >> 1, h = sl & 1;
        if (p < cap) {
            float* A = (float*)&TA[p * Nn + slot];
            A[h] = px; A[2 + h] = py;
            float* Bq = (float*)&TBt[p * Nn + slot];
            Bq[h] = pz; Bq[2 + h] = pw;
            ((unsigned short*)&TI[p * Nn + slot])[h] = (unsigned short)(i * 16);
        }
    }

    redZ[i] = nz ? pz : 0.f;
    redW[i] = nz ? pw : 0.f;
    __syncthreads();
#pragma unroll
    for (int s = Nn / 2; s > 0; s >>= 1) {
        if (i < s) { redZ[i] += redZ[i + s]; redW[i] += redW[i + s]; }
        __syncthreads();
    }
    if (i == 0) {
        int tot = 0;
#pragma unroll
        for (int b = 0; b < 8; b++) tot += hist[b];
        if (rc) { g_recCnt[slot] = tot; g_ncoT[0][slot] = redZ[0]; g_dcoT[0][slot] = redW[0]; }
        else    { g_senCnt[slot] = tot; g_ncoT[1][slot] = redZ[0]; g_dcoT[1][slot] = redW[0]; }
    }
}

// ---------------------------------------------------------------------------
// P2: pad counts to warp max (multiple of 4), zero odd half-pair + dummies.
// ---------------------------------------------------------------------------
__global__ void pack_phase2() {
    const int t = threadIdx.x;
#pragma unroll
    for (int q = 0; q < 2; q++) {
        const int cap = q == 0 ? REC_CAP : SEN_CAP;
        int* Cnt      = q == 0 ? g_recCnt : g_senCnt;
        float4* TA    = q == 0 ? g_recA : g_senA;
        float4* TBt   = q == 0 ? g_recB : g_senB;
        unsigned* TI  = q == 0 ? g_recIdx : g_senIdx;

        int cnt_nz = Cnt[t];
        int myP = min((cnt_nz + 1) >> 1, cap);
        if ((cnt_nz & 1) && (cnt_nz >> 1) < cap) {
            int p = cnt_nz >> 1;
            float* A = (float*)&TA[p * Nn + t];  A[1] = 0.f; A[3] = 0.f;
            float* Bq = (float*)&TBt[p * Nn + t]; Bq[1] = 0.f; Bq[3] = 0.f;
            ((unsigned short*)&TI[p * Nn + t])[1] = 0;
        }
        int wm = myP;
#pragma unroll
        for (int off = 16; off > 0; off >>= 1)
            wm = max(wm, __shfl_xor_sync(0xffffffffu, wm, off));
        wm = min((wm + 3) & ~3, cap);
        for (int p = myP; p < wm; p++) {
            TA[p * Nn + t]  = make_float4(0.f, 0.f, 0.f, 0.f);
            TBt[p * Nn + t] = make_float4(0.f, 0.f, 0.f, 0.f);
            TI[p * Nn + t]  = 0u;
        }
        Cnt[t] = wm;
    }
}

// ---------------------------------------------------------------------------
// Main kernel: lane t handles column g_perm[t]; NB (3 or 4) batches per CTA,
// grid=296, 2 CTAs/SM, paired so each SM's batch total <= 7.
// Transposed state vsT[Nn][4]; f32 args, f16x2 tanh, f32x2 accumulation.
// ---------------------------------------------------------------------------

// CTA -> (batch offset, batch count). Pairs (b, b+148) sum to <= 7.
__device__ __forceinline__ void cta_span(int bid, int& b0, int& nb) {
    if (bid < 128)      { nb = 4; b0 = 4 * bid; }
    else if (bid < 148) { nb = 3; b0 = 512 + 3 * (bid - 128); }
    else if (bid < 276) { nb = 3; b0 = 572 + 3 * (bid - 148); }
    else if (bid < 284) { nb = 4; b0 = 956 + 4 * (bid - 276); }
    else                { nb = 3; b0 = 988 + 3 * (bid - 284); }
}

template <int NB>
__device__ __forceinline__ void step(unsigned id, float4 pa, float4 pb,
                                     const char* vbase, ull* num2, ull* den2) {
    const char* p0 = vbase + (id & 0xFFFFu);
    const char* p1 = vbase + (id >> 16);
    float va[NB], vb[NB];
    if (NB == 4) {
        float4 x = *(const float4*)p0; va[0]=x.x; va[1]=x.y; va[2]=x.z; va[3]=x.w;
        float4 y = *(const float4*)p1; vb[0]=y.x; vb[1]=y.y; vb[2]=y.z; vb[3]=y.w;
    } else {
        float2 x = *(const float2*)p0; va[0]=x.x; va[1]=x.y; va[2]=*(const float*)(p0+8);
        float2 y = *(const float2*)p1; vb[0]=y.x; vb[1]=y.y; vb[2]=*(const float*)(p1+8);
    }
    ull pz2 = pk2(pb.x, pb.y), pw2 = pk2(pb.z, pb.w);
#pragma unroll
    for (int q = 0; q < NB; q++) {
        float a0 = fmaf(pa.x, va[q], pa.z);
        float a1 = fmaf(pa.y, vb[q], pa.w);
        __half2 th = fast_tanh_h2(__floats2half2_rn(a0, a1));
        ull t2 = pk2(__low2float(th), __high2float(th));
        num2[q] = fma2(pz2, t2, num2[q]);
        den2[q] = fma2(pw2, t2, den2[q]);
    }
}

template <int NB>
__device__ __forceinline__ void pass(const float4* __restrict__ TA,
                                     const float4* __restrict__ TB2,
                                     const unsigned* __restrict__ TI,
                                     int cnt, int t, const char* vbase,
                                     ull* num2, ull* den2) {
    unsigned i0 = TI[0 * Nn + t], i1 = TI[1 * Nn + t];
    float4 a0 = TA[0 * Nn + t], a1 = TA[1 * Nn + t];
    float4 b0 = TB2[0 * Nn + t], b1 = TB2[1 * Nn + t];
    for (int k = 0; k < cnt; k += 4) {
        int k2 = k + 2;
        unsigned i2 = TI[k2 * Nn + t], i3 = TI[(k2 + 1) * Nn + t];
        float4 a2 = TA[k2 * Nn + t], a3 = TA[(k2 + 1) * Nn + t];
        float4 b2 = TB2[k2 * Nn + t], b3 = TB2[(k2 + 1) * Nn + t];
        step<NB>(i0, a0, b0, vbase, num2, den2);
        step<NB>(i1, a1, b1, vbase, num2, den2);
        int k4 = (k + 4 < cnt) ? k + 4 : 0;
        i0 = TI[k4 * Nn + t]; i1 = TI[(k4 + 1) * Nn + t];
        a0 = TA[k4 * Nn + t]; a1 = TA[(k4 + 1) * Nn + t];
        b0 = TB2[k4 * Nn + t]; b1 = TB2[(k4 + 1) * Nn + t];
        step<NB>(i2, a2, b2, vbase, num2, den2);
        step<NB>(i3, a3, b3, vbase, num2, den2);
    }
}

template <int NB>
__device__ __forceinline__ void ltc_body(
        int t, int n, int b0, float (*xsT)[4], float (*vsT)[4],
        const float* __restrict__ inputs, const float* __restrict__ states,
        const float* __restrict__ gleak,  const float* __restrict__ vleak,
        const float* __restrict__ cm,
        const float* __restrict__ input_w, const float* __restrict__ input_b,
        const float* __restrict__ output_w, const float* __restrict__ output_b,
        float* __restrict__ out) {
    for (int q = t; q < NB * Ss; q += 256) {
        int tb = q / Ss, s = q - tb * Ss;
        xsT[s][tb] = fmaf(inputs[(b0 + tb) * Ss + s], input_w[s], input_b[s]);
    }

    float vreg[NB];
#pragma unroll
    for (int tb = 0; tb < NB; tb++) {
        vreg[tb] = states[(b0 + tb) * Nn + n];
        vsT[n][tb] = vreg[tb];
    }

    const float gl  = gleak[n];
    const float cmt = cm[n] * (float)NU;
    const float gv  = gl * vleak[n];
    const float nco = g_ncoT[0][t] + g_ncoT[1][t];
    const float dco = g_dcoT[0][t] + g_dcoT[1][t] + gl + cmt + 1e-8f;
    const int recCnt = g_recCnt[t];
    const int senCnt = g_senCnt[t];
    const char* xbase = (const char*)xsT;
    const char* vbase = (const char*)vsT;

    __syncthreads();

    ull num2[NB], den2[NB];
#pragma unroll
    for (int tb = 0; tb < NB; tb++) { num2[tb] = 0; den2[tb] = 0; }
    pass<NB>(g_senA, g_senB, g_senIdx, senCnt, t, xbase, num2, den2);

    float sn[NB], sd[NB];
#pragma unroll
    for (int tb = 0; tb < NB; tb++) {
        float2 a = unpk2(num2[tb]), b = unpk2(den2[tb]);
        sn[tb] = a.x + a.y + nco;
        sd[tb] = b.x + b.y + dco;
    }

    for (int u = 0; u < NU; u++) {
#pragma unroll
        for (int tb = 0; tb < NB; tb++) {
            num2[tb] = pk2(sn[tb], 0.f);
            den2[tb] = pk2(sd[tb], 0.f);
        }
        pass<NB>(g_recA, g_recB, g_recIdx, recCnt, t, vbase, num2, den2);

        __syncthreads();
#pragma unroll
        for (int tb = 0; tb < NB; tb++) {
            float2 a = unpk2(num2[tb]), b = unpk2(den2[tb]);
            float numerator = fmaf(cmt, vreg[tb], gv * (a.x + a.y));
            vreg[tb] = __fdividef(numerator, b.x + b.y);
            vsT[n][tb] = vreg[tb];
        }
        __syncthreads();
    }

#pragma unroll
    for (int tb = 0; tb < NB; tb++) {
        int b = b0 + tb;
        out[Bb * Mm + b * Nn + n] = vreg[tb];
        if (n < Mm)
            out[b * Mm + n] = fmaf(vreg[tb], output_w[n], output_b[n]);
    }
}

__global__ void __launch_bounds__(256, 2)
ltc_kernel(const float* __restrict__ inputs,
           const float* __restrict__ states,
           const float* __restrict__ gleak,
           const float* __restrict__ vleak,
           const float* __restrict__ cm,
           const float* __restrict__ input_w,
           const float* __restrict__ input_b,
           const float* __restrict__ output_w,
           const float* __restrict__ output_b,
           float* __restrict__ out) {
    __shared__ __align__(16) float xsT[Ss][4];
    __shared__ __align__(16) float vsT[Nn][4];

    const int t = threadIdx.x;
    const int n = g_perm[t];
    int b0, nb;
    cta_span(blockIdx.x, b0, nb);

    if (nb == 4)
        ltc_body<4>(t, n, b0, xsT, vsT, inputs, states, gleak, vleak, cm,
                    input_w, input_b, output_w, output_b, out);
    else
        ltc_body<3>(t, n, b0, xsT, vsT, inputs, states, gleak, vleak, cm,
                    input_w, input_b, output_w, output_b, out);
}

// ---------------------------------------------------------------------------
extern "C" void kernel_launch(void* const* d_in, const int* in_sizes, int n_in,
                              void* d_out, int out_size) {
    const float* inputs   = (const float*)d_in[0];
    const float* states   = (const float*)d_in[1];
    const float* gleak    = (const float*)d_in[2];
    const float* vleak    = (const float*)d_in[3];
    const float* cm       = (const float*)d_in[4];
    const float* sigma    = (const float*)d_in[5];
    const float* mu       = (const float*)d_in[6];
    const float* w        = (const float*)d_in[7];
    const float* erev     = (const float*)d_in[8];
    const float* ssigma   = (const float*)d_in[9];
    const float* smu      = (const float*)d_in[10];
    const float* sw       = (const float*)d_in[11];
    const float* serev    = (const float*)d_in[12];
    const float* input_w  = (const float*)d_in[13];
    const float* input_b  = (const float*)d_in[14];
    const float* output_w = (const float*)d_in[15];
    const float* output_b = (const float*)d_in[16];
    const float* mask     = (const float*)d_in[17];
    const float* smask    = (const float*)d_in[18];
    float* out = (float*)d_out;

    pack_count<<<Nn, 256>>>(mask);
    pack_rank<<<1, 256>>>();
    dim3 pgrid(Nn, 2);
    pack_phase1<<<pgrid, 256>>>(sigma, mu, w, erev, mask,
                                ssigma, smu, sw, serev, smask);
    pack_phase2<<<1, 256>>>();
    ltc_kernel<<<GRID, 256>>>(inputs, states, gleak, vleak, cm,
                              input_w, input_b, output_w, output_b, out);
}

// round 11
// speedup vs baseline: 1.2345x; 1.2345x over previous
#include <cuda_runtime.h>
#include <cuda_fp16.h>

#define Bb 1024
#define Ss 128
#define Nn 256
#define Mm 32
#define NU 6
#define TB 4
#define GRID (Bb / TB)     // 256 CTAs, 2 per SM  (R9 proven config)
#define REC_CAP 96
#define SEN_CAP 56

typedef unsigned long long ull;

// Compacted per-column pair tables, indexed by SLOT (count-sorted lane).
// A = { px_a, px_b, py_a, py_b }  (px = 0.5*sigma, py = -0.5*sigma*mu)
// B = { pz_a, pz_b, pw_a, pw_b }  (pz = 0.5*w*erev, pw = 0.5*w; mask==1 entries only)
// Idx = packed ushort2 byte offsets (i*16) into the transposed state array.
__device__ float4   g_recA[REC_CAP * Nn];
__device__ float4   g_recB[REC_CAP * Nn];
__device__ unsigned g_recIdx[REC_CAP * Nn];
__device__ float4   g_senA[SEN_CAP * Nn];
__device__ float4   g_senB[SEN_CAP * Nn];
__device__ unsigned g_senIdx[SEN_CAP * Nn];
__device__ int      g_recCnt[Nn], g_senCnt[Nn];   // per SLOT: padded pair count (mult of 4)
__device__ float    g_ncoT[2][Nn], g_dcoT[2][Nn]; // per SLOT
__device__ int      g_perm[Nn];                   // slot -> column
__device__ int      g_rank[Nn];                   // column -> slot
__device__ int      g_cnt0[2][Nn];                // per-column nonzero count [0]=rec [1]=sen

__device__ __forceinline__ __half2 fast_tanh_h2(__half2 x) {
    unsigned r, a = *reinterpret_cast<unsigned*>(&x);
    asm("tanh.approx.f16x2 %0, %1;" : "=r"(r) : "r"(a));
    return *reinterpret_cast<__half2*>(&r);
}
__device__ __forceinline__ ull pk2(float lo, float hi) {
    ull r; asm("mov.b64 %0, {%1, %2};" : "=l"(r) : "f"(lo), "f"(hi)); return r;
}
__device__ __forceinline__ float2 unpk2(ull a) {
    float lo, hi; asm("mov.b64 {%0, %1}, %2;" : "=f"(lo), "=f"(hi) : "l"(a));
    return make_float2(lo, hi);
}
__device__ __forceinline__ ull fma2(ull a, ull b, ull c) {
    ull d; asm("fma.rn.f32x2 %0, %1, %2, %3;" : "=l"(d) : "l"(a), "l"(b), "l"(c));
    return d;
}

// ---------------------------------------------------------------------------
// P-count: per-column nonzero counts for BOTH tables. grid (Nn, 2).
// ---------------------------------------------------------------------------
__global__ void pack_count(const float* __restrict__ mask,
                           const float* __restrict__ smask) {
    const int n   = blockIdx.x;
    const bool rc = (blockIdx.y == 0);
    const int D   = rc ? Nn : Ss;
    const float* m = rc ? mask : smask;
    __shared__ int red[Nn];
    const int i = threadIdx.x;
    red[i] = (i < D && m[i * Nn + n] != 0.f) ? 1 : 0;
    __syncthreads();
#pragma unroll
    for (int s = Nn / 2; s > 0; s >>= 1) {
        if (i < s) red[i] += red[i + s];
        __syncthreads();
    }
    if (i == 0) g_cnt0[rc ? 0 : 1][n] = red[0];
}

// ---------------------------------------------------------------------------
// P-rank: rank columns (rec count desc, tie index asc) -> perm/rank,
// then compute padded warp-max pair counts per slot for rec AND sen.
// 1 block, 256 threads. Deterministic (same perm as R9).
// ---------------------------------------------------------------------------
__global__ void pack_rank() {
    __shared__ int cnt[Nn];
    __shared__ int sperm[Nn];
    const int n = threadIdx.x;
    cnt[n] = g_cnt0[0][n];
    __syncthreads();
    const int c = cnt[n];
    int rank = 0;
    for (int m = 0; m < Nn; m++) {
        int cm = cnt[m];
        if (cm > c || (cm == c && m < n)) rank++;
    }
    g_rank[n] = rank;
    sperm[rank] = n;
    __syncthreads();
    g_perm[n] = sperm[n];

    const int t = n;              // this thread now acts as slot t
    const int col = sperm[t];
#pragma unroll
    for (int q = 0; q < 2; q++) {
        const int cap = q == 0 ? REC_CAP : SEN_CAP;
        int raw = g_cnt0[q][col];
        int myP = min((raw + 1) >> 1, cap);
        int wm = myP;
#pragma unroll
        for (int off = 16; off > 0; off >>= 1)
            wm = max(wm, __shfl_xor_sync(0xffffffffu, wm, off));
        wm = min((wm + 3) & ~3, cap);
        if (q == 0) g_recCnt[t] = wm; else g_senCnt[t] = wm;
    }
}

// ---------------------------------------------------------------------------
// P1: one block per column; compact nonzeros into slot-indexed tables AND
// zero odd half-pair + dummy pairs up to the padded count (old phase2 work,
// now parallel). Residue buckets by i&7 rotated by slot&7, ascending i.
// ---------------------------------------------------------------------------
__global__ void pack_phase1(const float* __restrict__ sigma, const float* __restrict__ mu,
                            const float* __restrict__ w,     const float* __restrict__ erev,
                            const float* __restrict__ mask,
                            const float* __restrict__ ssigma, const float* __restrict__ smu,
                            const float* __restrict__ sw,     const float* __restrict__ serev,
                            const float* __restrict__ smask) {
    const int n   = blockIdx.x;
    const bool rc = (blockIdx.y == 0);
    const int D   = rc ? Nn : Ss;
    const int cap = rc ? REC_CAP : SEN_CAP;
    const int i   = threadIdx.x;
    const int slot = g_rank[n];

    float4*   TA = rc ? g_recA : g_senA;
    float4*   TBt = rc ? g_recB : g_senB;
    unsigned* TI = rc ? g_recIdx : g_senIdx;

    __shared__ int hist[8];
    __shared__ unsigned char flag[Nn];
    __shared__ float redZ[Nn], redW[Nn];

    if (i < 8) hist[i] = 0;
    float mv = 0.f, sgv = 0.f, muv = 0.f, wv = 0.f, ev = 0.f;
    if (i < D) {
        if (rc) {
            mv = mask[i * Nn + n];  sgv = sigma[i * Nn + n];  muv = mu[i * Nn + n];
            wv = w[i * Nn + n];     ev  = erev[i * Nn + n];
        } else {
            mv = smask[i * Nn + n]; sgv = ssigma[i * Nn + n]; muv = smu[i * Nn + n];
            wv = sw[i * Nn + n];    ev  = serev[i * Nn + n];
        }
    }
    const bool nz = (i < D) && (mv != 0.f);
    flag[i] = nz ? 1 : 0;
    __syncthreads();
    if (nz) atomicAdd(&hist[i & 7], 1);
    __syncthreads();

    float px = 0.5f * sgv;
    float py = -px * muv;
    float pw = 0.5f * wv;
    float pz = pw * ev;

    if (nz) {
        const int r0 = slot & 7;
        const int myPr = ((i & 7) - r0) & 7;
        int start = 0;
#pragma unroll
        for (int b = 0; b < 8; b++)
            if ((((b - r0) & 7)) < myPr) start += hist[b];
        int rank = 0;
        for (int j = (i & 7); j < i; j += 8) rank += flag[j];
        int sl = start + rank;
        int p = sl >> 1, h = sl & 1;
        if (p < cap) {
            float* A = (float*)&TA[p * Nn + slot];
            A[h] = px; A[2 + h] = py;
            float* Bq = (float*)&TBt[p * Nn + slot];
            Bq[h] = pz; Bq[2 + h] = pw;
            ((unsigned short*)&TI[p * Nn + slot])[h] = (unsigned short)(i * 16);
        }
    }

    redZ[i] = nz ? pz : 0.f;
    redW[i] = nz ? pw : 0.f;
    __syncthreads();
#pragma unroll
    for (int s = Nn / 2; s > 0; s >>= 1) {
        if (i < s) { redZ[i] += redZ[i + s]; redW[i] += redW[i + s]; }
        __syncthreads();
    }

    // totals + padding (old phase2, now per-column parallel)
    int tot = 0;
#pragma unroll
    for (int b = 0; b < 8; b++) tot += hist[b];
    const int wm = rc ? g_recCnt[slot] : g_senCnt[slot];
    const int myP = min((tot + 1) >> 1, cap);

    if (i == 0) {
        if (rc) { g_ncoT[0][slot] = redZ[0]; g_dcoT[0][slot] = redW[0]; }
        else    { g_ncoT[1][slot] = redZ[0]; g_dcoT[1][slot] = redW[0]; }
        if ((tot & 1) && (tot >> 1) < cap) {     // zero the stale odd half
            int p = tot >> 1;
            float* A = (float*)&TA[p * Nn + slot];  A[1] = 0.f; A[3] = 0.f;
            float* Bq = (float*)&TBt[p * Nn + slot]; Bq[1] = 0.f; Bq[3] = 0.f;
            ((unsigned short*)&TI[p * Nn + slot])[1] = 0;
        }
    }
    for (int p = myP + i; p < wm; p += blockDim.x) {   // dummy pairs
        TA[p * Nn + slot]  = make_float4(0.f, 0.f, 0.f, 0.f);
        TBt[p * Nn + slot] = make_float4(0.f, 0.f, 0.f, 0.f);
        TI[p * Nn + slot]  = 0u;
    }
}

// ---------------------------------------------------------------------------
// Main kernel: EXACT R9 body. Lane t handles column g_perm[t]; TB=4 batches,
// 2 CTAs/SM. Transposed state vsT[Nn][4]; per-i gather = one LDS.128.
// f32 args, f16x2 tanh over i-pairs, f32x2 accumulation.
// ---------------------------------------------------------------------------

#define EVAL1(PA, PZ2, PW2, VA, VB, NUM2, DEN2)                              \
    {                                                                        \
        float a0 = fmaf(PA.x, VA, PA.z);                                     \
        float a1 = fmaf(PA.y, VB, PA.w);                                     \
        __half2 t = fast_tanh_h2(__floats2half2_rn(a0, a1));                 \
        ull t2 = pk2(__low2float(t), __high2float(t));                       \
        NUM2 = fma2(PZ2, t2, NUM2);                                          \
        DEN2 = fma2(PW2, t2, DEN2);                                          \
    }

#define STEP(ID, PA, PB, VBASE, NUM2A, DEN2A)                                \
    {                                                                        \
        float4 va = *(const float4*)(VBASE + (ID & 0xFFFFu));                \
        float4 vb = *(const float4*)(VBASE + (ID >> 16));                    \
        ull pz2 = pk2(PB.x, PB.y), pw2 = pk2(PB.z, PB.w);                    \
        EVAL1(PA, pz2, pw2, va.x, vb.x, NUM2A[0], DEN2A[0])                  \
        EVAL1(PA, pz2, pw2, va.y, vb.y, NUM2A[1], DEN2A[1])                  \
        EVAL1(PA, pz2, pw2, va.z, vb.z, NUM2A[2], DEN2A[2])                  \
        EVAL1(PA, pz2, pw2, va.w, vb.w, NUM2A[3], DEN2A[3])                  \
    }

#define PASS(TA_, TB2_, TI_, CNT, VBASE, NUM2A, DEN2A)                       \
    {                                                                        \
        unsigned i0_ = TI_[0 * Nn + t], i1_ = TI_[1 * Nn + t];               \
        float4 a0_ = TA_[0 * Nn + t], a1_ = TA_[1 * Nn + t];                 \
        float4 b0_ = TB2_[0 * Nn + t], b1_ = TB2_[1 * Nn + t];               \
        for (int k = 0; k < CNT; k += 4) {                                   \
            int k2 = k + 2;                                                  \
            unsigned i2_ = TI_[k2 * Nn + t], i3_ = TI_[(k2 + 1) * Nn + t];   \
            float4 a2_ = TA_[k2 * Nn + t], a3_ = TA_[(k2 + 1) * Nn + t];     \
            float4 b2_ = TB2_[k2 * Nn + t], b3_ = TB2_[(k2 + 1) * Nn + t];   \
            STEP(i0_, a0_, b0_, VBASE, NUM2A, DEN2A)                         \
            STEP(i1_, a1_, b1_, VBASE, NUM2A, DEN2A)                         \
            int k4 = (k + 4 < CNT) ? k + 4 : 0;                              \
            i0_ = TI_[k4 * Nn + t]; i1_ = TI_[(k4 + 1) * Nn + t];            \
            a0_ = TA_[k4 * Nn + t]; a1_ = TA_[(k4 + 1) * Nn + t];            \
            b0_ = TB2_[k4 * Nn + t]; b1_ = TB2_[(k4 + 1) * Nn + t];          \
            STEP(i2_, a2_, b2_, VBASE, NUM2A, DEN2A)                         \
            STEP(i3_, a3_, b3_, VBASE, NUM2A, DEN2A)                         \
        }                                                                    \
    }

__global__ void __launch_bounds__(256, 2)
ltc_kernel(const float* __restrict__ inputs,
           const float* __restrict__ states,
           const float* __restrict__ gleak,
           const float* __restrict__ vleak,
           const float* __restrict__ cm,
           const float* __restrict__ input_w,
           const float* __restrict__ input_b,
           const float* __restrict__ output_w,
           const float* __restrict__ output_b,
           float* __restrict__ out) {
    __shared__ __align__(16) float xsT[Ss][TB];
    __shared__ __align__(16) float vsT[Nn][TB];

    const int t  = threadIdx.x;
    const int n  = g_perm[t];                // column handled by this lane
    const int b0 = blockIdx.x * TB;

    for (int q = threadIdx.x; q < TB * Ss; q += 256) {
        int tb = q / Ss, s = q - tb * Ss;
        xsT[s][tb] = fmaf(inputs[(b0 + tb) * Ss + s], input_w[s], input_b[s]);
    }

    float vreg[TB];
#pragma unroll
    for (int tb = 0; tb < TB; tb++)
        vreg[tb] = states[(b0 + tb) * Nn + n];
    *(float4*)&vsT[n][0] = make_float4(vreg[0], vreg[1], vreg[2], vreg[3]);

    const float gl  = gleak[n];
    const float cmt = cm[n] * (float)NU;
    const float gv  = gl * vleak[n];
    const float nco = g_ncoT[0][t] + g_ncoT[1][t];
    const float dco = g_dcoT[0][t] + g_dcoT[1][t] + gl + cmt + 1e-8f;
    const int recCnt = g_recCnt[t];
    const int senCnt = g_senCnt[t];
    const char* xbase = (const char*)xsT;
    const char* vbase = (const char*)vsT;

    __syncthreads();

    // ---- sensory pass (variable part; once)
    ull num2[TB], den2[TB];
#pragma unroll
    for (int tb = 0; tb < TB; tb++) { num2[tb] = 0; den2[tb] = 0; }
    PASS(g_senA, g_senB, g_senIdx, senCnt, xbase, num2, den2)

    float sn[TB], sd[TB];
#pragma unroll
    for (int tb = 0; tb < TB; tb++) {
        float2 a = unpk2(num2[tb]), b = unpk2(den2[tb]);
        sn[tb] = a.x + a.y + nco;
        sd[tb] = b.x + b.y + dco;
    }

    // ---- 6 unfolds
    for (int u = 0; u < NU; u++) {
#pragma unroll
        for (int tb = 0; tb < TB; tb++) {
            num2[tb] = pk2(sn[tb], 0.f);
            den2[tb] = pk2(sd[tb], 0.f);
        }
        PASS(g_recA, g_recB, g_recIdx, recCnt, vbase, num2, den2)

        __syncthreads();   // all reads of vsT done
#pragma unroll
        for (int tb = 0; tb < TB; tb++) {
            float2 a = unpk2(num2[tb]), b = unpk2(den2[tb]);
            float numerator = fmaf(cmt, vreg[tb], gv * (a.x + a.y));
            vreg[tb] = __fdividef(numerator, b.x + b.y);
        }
        *(float4*)&vsT[n][0] = make_float4(vreg[0], vreg[1], vreg[2], vreg[3]);
        __syncthreads();   // new state visible
    }

    // ---- outputs: [B*M] motor outputs, then [B*N] final states
#pragma unroll
    for (int tb = 0; tb < TB; tb++) {
        int b = b0 + tb;
        out[Bb * Mm + b * Nn + n] = vreg[tb];
        if (n < Mm)
            out[b * Mm + n] = fmaf(vreg[tb], output_w[n], output_b[n]);
    }
}

// ---------------------------------------------------------------------------
extern "C" void kernel_launch(void* const* d_in, const int* in_sizes, int n_in,
                              void* d_out, int out_size) {
    const float* inputs   = (const float*)d_in[0];
    const float* states   = (const float*)d_in[1];
    const float* gleak    = (const float*)d_in[2];
    const float* vleak    = (const float*)d_in[3];
    const float* cm       = (const float*)d_in[4];
    const float* sigma    = (const float*)d_in[5];
    const float* mu       = (const float*)d_in[6];
    const float* w        = (const float*)d_in[7];
    const float* erev     = (const float*)d_in[8];
    const float* ssigma   = (const float*)d_in[9];
    const float* smu      = (const float*)d_in[10];
    const float* sw       = (const float*)d_in[11];
    const float* serev    = (const float*)d_in[12];
    const float* input_w  = (const float*)d_in[13];
    const float* input_b  = (const float*)d_in[14];
    const float* output_w = (const float*)d_in[15];
    const float* output_b = (const float*)d_in[16];
    const float* mask     = (const float*)d_in[17];
    const float* smask    = (const float*)d_in[18];
    float* out = (float*)d_out;

    dim3 pgrid(Nn, 2);
    pack_count<<<pgrid, 256>>>(mask, smask);
    pack_rank<<<1, 256>>>();
    pack_phase1<<<pgrid, 256>>>(sigma, mu, w, erev, mask,
                                ssigma, smu, sw, serev, smask);
    ltc_kernel<<<GRID, 256>>>(inputs, states, gleak, vleak, cm,
                              input_w, input_b, output_w, output_b, out);
}

// round 12
// speedup vs baseline: 1.3092x; 1.0605x over previous
#include <cuda_runtime.h>
#include <cuda_fp16.h>

#define Bb 1024
#define Ss 128
#define Nn 256
#define Mm 32
#define NU 6
#define TB 4
#define GRID (Bb / TB)     // 256 CTAs, 2 per SM
#define REC_CAP 96
#define SEN_CAP 56

// Compacted per-column pair tables, indexed by SLOT (count-sorted lane).
// A = { px_a, px_b, py_a, py_b }  (px = 0.5*sigma, py = -0.5*sigma*mu)
// B = { pz_a, pz_b, pw_a, pw_b }  (pz = 0.5*w*erev, pw = 0.5*w; mask==1 entries only)
// Idx = packed ushort2 byte offsets (i*16) into the transposed state array.
__device__ float4   g_recA[REC_CAP * Nn];
__device__ float4   g_recB[REC_CAP * Nn];
__device__ unsigned g_recIdx[REC_CAP * Nn];
__device__ float4   g_senA[SEN_CAP * Nn];
__device__ float4   g_senB[SEN_CAP * Nn];
__device__ unsigned g_senIdx[SEN_CAP * Nn];
__device__ int      g_recCnt[Nn], g_senCnt[Nn];   // per SLOT: padded pair count (mult of 4)
__device__ float    g_ncoT[2][Nn], g_dcoT[2][Nn]; // per SLOT
__device__ int      g_perm[Nn];                   // slot -> column
__device__ int      g_rank[Nn];                   // column -> slot
__device__ int      g_cnt0[2][Nn];                // per-column nonzero count [0]=rec [1]=sen

__device__ __forceinline__ float fast_tanh(float x) {
    float y;
    asm("tanh.approx.f32 %0, %1;" : "=f"(y) : "f"(x));
    return y;
}

// ---------------------------------------------------------------------------
// P-count: per-column nonzero counts for BOTH tables. grid (Nn, 2).
// ---------------------------------------------------------------------------
__global__ void pack_count(const float* __restrict__ mask,
                           const float* __restrict__ smask) {
    const int n   = blockIdx.x;
    const bool rc = (blockIdx.y == 0);
    const int D   = rc ? Nn : Ss;
    const float* m = rc ? mask : smask;
    __shared__ int red[Nn];
    const int i = threadIdx.x;
    red[i] = (i < D && m[i * Nn + n] != 0.f) ? 1 : 0;
    __syncthreads();
#pragma unroll
    for (int s = Nn / 2; s > 0; s >>= 1) {
        if (i < s) red[i] += red[i + s];
        __syncthreads();
    }
    if (i == 0) g_cnt0[rc ? 0 : 1][n] = red[0];
}

// ---------------------------------------------------------------------------
// P-rank: rank columns (rec count desc, tie index asc) -> perm/rank,
// then compute padded warp-max pair counts per slot for rec AND sen.
// ---------------------------------------------------------------------------
__global__ void pack_rank() {
    __shared__ int cnt[Nn];
    __shared__ int sperm[Nn];
    const int n = threadIdx.x;
    cnt[n] = g_cnt0[0][n];
    __syncthreads();
    const int c = cnt[n];
    int rank = 0;
    for (int m = 0; m < Nn; m++) {
        int cm = cnt[m];
        if (cm > c || (cm == c && m < n)) rank++;
    }
    g_rank[n] = rank;
    sperm[rank] = n;
    __syncthreads();
    g_perm[n] = sperm[n];

    const int t = n;              // this thread now acts as slot t
    const int col = sperm[t];
#pragma unroll
    for (int q = 0; q < 2; q++) {
        const int cap = q == 0 ? REC_CAP : SEN_CAP;
        int raw = g_cnt0[q][col];
        int myP = min((raw + 1) >> 1, cap);
        int wm = myP;
#pragma unroll
        for (int off = 16; off > 0; off >>= 1)
            wm = max(wm, __shfl_xor_sync(0xffffffffu, wm, off));
        wm = min((wm + 3) & ~3, cap);
        if (q == 0) g_recCnt[t] = wm; else g_senCnt[t] = wm;
    }
}

// ---------------------------------------------------------------------------
// P1: one block per column; compact nonzeros into slot-indexed tables AND
// zero odd half-pair + dummy pairs up to the padded count.
// Residue buckets by i&7 rotated by slot&7, ascending i within bucket.
// ---------------------------------------------------------------------------
__global__ void pack_phase1(const float* __restrict__ sigma, const float* __restrict__ mu,
                            const float* __restrict__ w,     const float* __restrict__ erev,
                            const float* __restrict__ mask,
                            const float* __restrict__ ssigma, const float* __restrict__ smu,
                            const float* __restrict__ sw,     const float* __restrict__ serev,
                            const float* __restrict__ smask) {
    const int n   = blockIdx.x;
    const bool rc = (blockIdx.y == 0);
    const int D   = rc ? Nn : Ss;
    const int cap = rc ? REC_CAP : SEN_CAP;
    const int i   = threadIdx.x;
    const int slot = g_rank[n];

    float4*   TA = rc ? g_recA : g_senA;
    float4*   TBt = rc ? g_recB : g_senB;
    unsigned* TI = rc ? g_recIdx : g_senIdx;

    __shared__ int hist[8];
    __shared__ unsigned char flag[Nn];
    __shared__ float redZ[Nn], redW[Nn];

    if (i < 8) hist[i] = 0;
    float mv = 0.f, sgv = 0.f, muv = 0.f, wv = 0.f, ev = 0.f;
    if (i < D) {
        if (rc) {
            mv = mask[i * Nn + n];  sgv = sigma[i * Nn + n];  muv = mu[i * Nn + n];
            wv = w[i * Nn + n];     ev  = erev[i * Nn + n];
        } else {
            mv = smask[i * Nn + n]; sgv = ssigma[i * Nn + n]; muv = smu[i * Nn + n];
            wv = sw[i * Nn + n];    ev  = serev[i * Nn + n];
        }
    }
    const bool nz = (i < D) && (mv != 0.f);
    flag[i] = nz ? 1 : 0;
    __syncthreads();
    if (nz) atomicAdd(&hist[i & 7], 1);
    __syncthreads();

    float px = 0.5f * sgv;
    float py = -px * muv;
    float pw = 0.5f * wv;
    float pz = pw * ev;

    if (nz) {
        const int r0 = slot & 7;
        const int myPr = ((i & 7) - r0) & 7;
        int start = 0;
#pragma unroll
        for (int b = 0; b < 8; b++)
            if ((((b - r0) & 7)) < myPr) start += hist[b];
        int rank = 0;
        for (int j = (i & 7); j < i; j += 8) rank += flag[j];
        int sl = start + rank;
        int p = sl >> 1, h = sl & 1;
        if (p < cap) {
            float* A = (float*)&TA[p * Nn + slot];
            A[h] = px; A[2 + h] = py;
            float* Bq = (float*)&TBt[p * Nn + slot];
            Bq[h] = pz; Bq[2 + h] = pw;
            ((unsigned short*)&TI[p * Nn + slot])[h] = (unsigned short)(i * 16);
        }
    }

    redZ[i] = nz ? pz : 0.f;
    redW[i] = nz ? pw : 0.f;
    __syncthreads();
#pragma unroll
    for (int s = Nn / 2; s > 0; s >>= 1) {
        if (i < s) { redZ[i] += redZ[i + s]; redW[i] += redW[i + s]; }
        __syncthreads();
    }

    int tot = 0;
#pragma unroll
    for (int b = 0; b < 8; b++) tot += hist[b];
    const int wm = rc ? g_recCnt[slot] : g_senCnt[slot];
    const int myP = min((tot + 1) >> 1, cap);

    if (i == 0) {
        if (rc) { g_ncoT[0][slot] = redZ[0]; g_dcoT[0][slot] = redW[0]; }
        else    { g_ncoT[1][slot] = redZ[0]; g_dcoT[1][slot] = redW[0]; }
        if ((tot & 1) && (tot >> 1) < cap) {     // zero the stale odd half
            int p = tot >> 1;
            float* A = (float*)&TA[p * Nn + slot];  A[1] = 0.f; A[3] = 0.f;
            float* Bq = (float*)&TBt[p * Nn + slot]; Bq[1] = 0.f; Bq[3] = 0.f;
            ((unsigned short*)&TI[p * Nn + slot])[1] = 0;
        }
    }
    for (int p = myP + i; p < wm; p += blockDim.x) {   // dummy pairs
        TA[p * Nn + slot]  = make_float4(0.f, 0.f, 0.f, 0.f);
        TBt[p * Nn + slot] = make_float4(0.f, 0.f, 0.f, 0.f);
        TI[p * Nn + slot]  = 0u;
    }
}

// ---------------------------------------------------------------------------
// Main kernel: lane t handles column g_perm[t]; TB=4 batches, 2 CTAs/SM.
// Transposed state vsT[Nn][4]; per-i gather = one LDS.128.
// ALL-f32 path: FFMA arg -> MUFU tanh.f32 -> 2x FFMA accumulate.
// Short dependency chains (no f16 conversions), 8-way ILP per STEP.
// ---------------------------------------------------------------------------

#define EVAL1(PXc, PYc, PZc, PWc, V, NUM, DEN)                               \
    {                                                                        \
        float tnh = fast_tanh(fmaf(PXc, V, PYc));                            \
        NUM = fmaf(PZc, tnh, NUM);                                           \
        DEN = fmaf(PWc, tnh, DEN);                                           \
    }

#define STEP(ID, PA, PB, VBASE, NUMA, DENA)                                  \
    {                                                                        \
        float4 va = *(const float4*)(VBASE + (ID & 0xFFFFu));                \
        float4 vb = *(const float4*)(VBASE + (ID >> 16));                    \
        EVAL1(PA.x, PA.z, PB.x, PB.z, va.x, NUMA[0], DENA[0])                \
        EVAL1(PA.y, PA.w, PB.y, PB.w, vb.x, NUMA[0], DENA[0])                \
        EVAL1(PA.x, PA.z, PB.x, PB.z, va.y, NUMA[1], DENA[1])                \
        EVAL1(PA.y, PA.w, PB.y, PB.w, vb.y, NUMA[1], DENA[1])                \
        EVAL1(PA.x, PA.z, PB.x, PB.z, va.z, NUMA[2], DENA[2])                \
        EVAL1(PA.y, PA.w, PB.y, PB.w, vb.z, NUMA[2], DENA[2])                \
        EVAL1(PA.x, PA.z, PB.x, PB.z, va.w, NUMA[3], DENA[3])                \
        EVAL1(PA.y, PA.w, PB.y, PB.w, vb.w, NUMA[3], DENA[3])                \
    }

// CNT is a multiple of 4 and >= 4 (warp-uniform). Copy-free rotated pipeline.
#define PASS(TA_, TB2_, TI_, CNT, VBASE, NUMA, DENA)                         \
    {                                                                        \
        unsigned i0_ = TI_[0 * Nn + t], i1_ = TI_[1 * Nn + t];               \
        float4 a0_ = TA_[0 * Nn + t], a1_ = TA_[1 * Nn + t];                 \
        float4 b0_ = TB2_[0 * Nn + t], b1_ = TB2_[1 * Nn + t];               \
        for (int k = 0; k < CNT; k += 4) {                                   \
            int k2 = k + 2;                                                  \
            unsigned i2_ = TI_[k2 * Nn + t], i3_ = TI_[(k2 + 1) * Nn + t];   \
            float4 a2_ = TA_[k2 * Nn + t], a3_ = TA_[(k2 + 1) * Nn + t];     \
            float4 b2_ = TB2_[k2 * Nn + t], b3_ = TB2_[(k2 + 1) * Nn + t];   \
            STEP(i0_, a0_, b0_, VBASE, NUMA, DENA)                           \
            STEP(i1_, a1_, b1_, VBASE, NUMA, DENA)                           \
            int k4 = (k + 4 < CNT) ? k + 4 : 0;                              \
            i0_ = TI_[k4 * Nn + t]; i1_ = TI_[(k4 + 1) * Nn + t];            \
            a0_ = TA_[k4 * Nn + t]; a1_ = TA_[(k4 + 1) * Nn + t];            \
            b0_ = TB2_[k4 * Nn + t]; b1_ = TB2_[(k4 + 1) * Nn + t];          \
            STEP(i2_, a2_, b2_, VBASE, NUMA, DENA)                           \
            STEP(i3_, a3_, b3_, VBASE, NUMA, DENA)                           \
        }                                                                    \
    }

__global__ void __launch_bounds__(256, 2)
ltc_kernel(const float* __restrict__ inputs,
           const float* __restrict__ states,
           const float* __restrict__ gleak,
           const float* __restrict__ vleak,
           const float* __restrict__ cm,
           const float* __restrict__ input_w,
           const float* __restrict__ input_b,
           const float* __restrict__ output_w,
           const float* __restrict__ output_b,
           float* __restrict__ out) {
    __shared__ __align__(16) float xsT[Ss][TB];
    __shared__ __align__(16) float vsT[Nn][TB];

    const int t  = threadIdx.x;
    const int n  = g_perm[t];                // column handled by this lane
    const int b0 = blockIdx.x * TB;

    for (int q = threadIdx.x; q < TB * Ss; q += 256) {
        int tb = q / Ss, s = q - tb * Ss;
        xsT[s][tb] = fmaf(inputs[(b0 + tb) * Ss + s], input_w[s], input_b[s]);
    }

    float vreg[TB];
#pragma unroll
    for (int tb = 0; tb < TB; tb++)
        vreg[tb] = states[(b0 + tb) * Nn + n];
    *(float4*)&vsT[n][0] = make_float4(vreg[0], vreg[1], vreg[2], vreg[3]);

    const float gl  = gleak[n];
    const float cmt = cm[n] * (float)NU;
    const float gv  = gl * vleak[n];
    const float nco = g_ncoT[0][t] + g_ncoT[1][t];
    const float dco = g_dcoT[0][t] + g_dcoT[1][t] + gl + cmt + 1e-8f;
    const int recCnt = g_recCnt[t];
    const int senCnt = g_senCnt[t];
    const char* xbase = (const char*)xsT;
    const char* vbase = (const char*)vsT;

    __syncthreads();

    // ---- sensory pass (variable part; once)
    float num[TB], den[TB];
#pragma unroll
    for (int tb = 0; tb < TB; tb++) { num[tb] = 0.f; den[tb] = 0.f; }
    PASS(g_senA, g_senB, g_senIdx, senCnt, xbase, num, den)

    float sn[TB], sd[TB];
#pragma unroll
    for (int tb = 0; tb < TB; tb++) {
        sn[tb] = num[tb] + nco;
        sd[tb] = den[tb] + dco;
    }

    // ---- 6 unfolds
    for (int u = 0; u < NU; u++) {
#pragma unroll
        for (int tb = 0; tb < TB; tb++) { num[tb] = sn[tb]; den[tb] = sd[tb]; }
        PASS(g_recA, g_recB, g_recIdx, recCnt, vbase, num, den)

        __syncthreads();   // all reads of vsT done
#pragma unroll
        for (int tb = 0; tb < TB; tb++) {
            float numerator = fmaf(cmt, vreg[tb], gv * num[tb]);
            vreg[tb] = __fdividef(numerator, den[tb]);
        }
        *(float4*)&vsT[n][0] = make_float4(vreg[0], vreg[1], vreg[2], vreg[3]);
        __syncthreads();   // new state visible
    }

    // ---- outputs: [B*M] motor outputs, then [B*N] final states
#pragma unroll
    for (int tb = 0; tb < TB; tb++) {
        int b = b0 + tb;
        out[Bb * Mm + b * Nn + n] = vreg[tb];
        if (n < Mm)
            out[b * Mm + n] = fmaf(vreg[tb], output_w[n], output_b[n]);
    }
}

// ---------------------------------------------------------------------------
extern "C" void kernel_launch(void* const* d_in, const int* in_sizes, int n_in,
                              void* d_out, int out_size) {
    const float* inputs   = (const float*)d_in[0];
    const float* states   = (const float*)d_in[1];
    const float* gleak    = (const float*)d_in[2];
    const float* vleak    = (const float*)d_in[3];
    const float* cm       = (const float*)d_in[4];
    const float* sigma    = (const float*)d_in[5];
    const float* mu       = (const float*)d_in[6];
    const float* w        = (const float*)d_in[7];
    const float* erev     = (const float*)d_in[8];
    const float* ssigma   = (const float*)d_in[9];
    const float* smu      = (const float*)d_in[10];
    const float* sw       = (const float*)d_in[11];
    const float* serev    = (const float*)d_in[12];
    const float* input_w  = (const float*)d_in[13];
    const float* input_b  = (const float*)d_in[14];
    const float* output_w = (const float*)d_in[15];
    const float* output_b = (const float*)d_in[16];
    const float* mask     = (const float*)d_in[17];
    const float* smask    = (const float*)d_in[18];
    float* out = (float*)d_out;

    dim3 pgrid(Nn, 2);
    pack_count<<<pgrid, 256>>>(mask, smask);
    pack_rank<<<1, 256>>>();
    pack_phase1<<<pgrid, 256>>>(sigma, mu, w, erev, mask,
                                ssigma, smu, sw, serev, smask);
    ltc_kernel<<<GRID, 256>>>(inputs, states, gleak, vleak, cm,
                              input_w, input_b, output_w, output_b, out);
}

// round 14
// speedup vs baseline: 1.3856x; 1.0583x over previous
#include <cuda_runtime.h>
#include <cuda_fp16.h>

#define Bb 1024
#define Ss 128
#define Nn 256
#define Mm 32
#define NU 6
#define TB 4
#define GRID (Bb / TB)     // 256 CTAs, 2 per SM
#define REC_CAP 96
#define SEN_CAP 56

// Compacted per-column pair tables, indexed by SLOT (count-sorted lane).
// A = { px_a, px_b, py_a, py_b }  (px = 0.5*sigma, py = -0.5*sigma*mu)
// B = { pz_a, pz_b }              (pz = 0.5*w*erev; erev=+-1 => pw = |pz|)
// Idx = packed ushort2 byte offsets (i*16) into the transposed state array.
__device__ float4   g_recA[REC_CAP * Nn];
__device__ float2   g_recB[REC_CAP * Nn];
__device__ unsigned g_recIdx[REC_CAP * Nn];
__device__ float4   g_senA[SEN_CAP * Nn];
__device__ float2   g_senB[SEN_CAP * Nn];
__device__ unsigned g_senIdx[SEN_CAP * Nn];
__device__ int      g_recCnt[Nn], g_senCnt[Nn];   // per SLOT: padded pair count (mult of 4)
__device__ float    g_ncoT[2][Nn], g_dcoT[2][Nn]; // per SLOT
__device__ int      g_perm[Nn];                   // slot -> column
__device__ int      g_rank[Nn];                   // column -> slot
__device__ int      g_cnt0[2][Nn];                // per-column nonzero count [0]=rec [1]=sen

__device__ __forceinline__ float fast_tanh(float x) {
    float y;
    asm("tanh.approx.f32 %0, %1;" : "=f"(y) : "f"(x));
    return y;
}

// ---------------------------------------------------------------------------
// P-count: per-column nonzero counts for BOTH tables. grid (Nn, 2).
// ---------------------------------------------------------------------------
__global__ void pack_count(const float* __restrict__ mask,
                           const float* __restrict__ smask) {
    const int n   = blockIdx.x;
    const bool rc = (blockIdx.y == 0);
    const int D   = rc ? Nn : Ss;
    const float* m = rc ? mask : smask;
    __shared__ int red[Nn];
    const int i = threadIdx.x;
    red[i] = (i < D && m[i * Nn + n] != 0.f) ? 1 : 0;
    __syncthreads();
#pragma unroll
    for (int s = Nn / 2; s > 0; s >>= 1) {
        if (i < s) red[i] += red[i + s];
        __syncthreads();
    }
    if (i == 0) g_cnt0[rc ? 0 : 1][n] = red[0];
}

// ---------------------------------------------------------------------------
// P-rank: rank columns (rec count desc, tie index asc) -> perm/rank,
// then compute padded warp-max pair counts per slot for rec AND sen.
// ---------------------------------------------------------------------------
__global__ void pack_rank() {
    __shared__ int cnt[Nn];
    __shared__ int sperm[Nn];
    const int n = threadIdx.x;
    cnt[n] = g_cnt0[0][n];
    __syncthreads();
    const int c = cnt[n];
    int rank = 0;
    for (int m = 0; m < Nn; m++) {
        int cm = cnt[m];
        if (cm > c || (cm == c && m < n)) rank++;
    }
    g_rank[n] = rank;
    sperm[rank] = n;
    __syncthreads();
    g_perm[n] = sperm[n];

    const int t = n;              // this thread now acts as slot t
    const int col = sperm[t];
#pragma unroll
    for (int q = 0; q < 2; q++) {
        const int cap = q == 0 ? REC_CAP : SEN_CAP;
        int raw = g_cnt0[q][col];
        int myP = min((raw + 1) >> 1, cap);
        int wm = myP;
#pragma unroll
        for (int off = 16; off > 0; off >>= 1)
            wm = max(wm, __shfl_xor_sync(0xffffffffu, wm, off));
        wm = min((wm + 3) & ~3, cap);
        if (q == 0) g_recCnt[t] = wm; else g_senCnt[t] = wm;
    }
}

// ---------------------------------------------------------------------------
// P1: one block per column; compact nonzeros into slot-indexed tables AND
// zero odd half-pair + dummy pairs up to the padded count.
// Residue buckets by i&7 rotated by slot&7, ascending i within bucket.
// ---------------------------------------------------------------------------
__global__ void pack_phase1(const float* __restrict__ sigma, const float* __restrict__ mu,
                            const float* __restrict__ w,     const float* __restrict__ erev,
                            const float* __restrict__ mask,
                            const float* __restrict__ ssigma, const float* __restrict__ smu,
                            const float* __restrict__ sw,     const float* __restrict__ serev,
                            const float* __restrict__ smask) {
    const int n   = blockIdx.x;
    const bool rc = (blockIdx.y == 0);
    const int D   = rc ? Nn : Ss;
    const int cap = rc ? REC_CAP : SEN_CAP;
    const int i   = threadIdx.x;
    const int slot = g_rank[n];

    float4*   TA = rc ? g_recA : g_senA;
    float2*   TBt = rc ? g_recB : g_senB;
    unsigned* TI = rc ? g_recIdx : g_senIdx;

    __shared__ int hist[8];
    __shared__ unsigned char flag[Nn];
    __shared__ float redZ[Nn], redW[Nn];

    if (i < 8) hist[i] = 0;
    float mv = 0.f, sgv = 0.f, muv = 0.f, wv = 0.f, ev = 0.f;
    if (i < D) {
        if (rc) {
            mv = mask[i * Nn + n];  sgv = sigma[i * Nn + n];  muv = mu[i * Nn + n];
            wv = w[i * Nn + n];     ev  = erev[i * Nn + n];
        } else {
            mv = smask[i * Nn + n]; sgv = ssigma[i * Nn + n]; muv = smu[i * Nn + n];
            wv = sw[i * Nn + n];    ev  = serev[i * Nn + n];
        }
    }
    const bool nz = (i < D) && (mv != 0.f);
    flag[i] = nz ? 1 : 0;
    __syncthreads();
    if (nz) atomicAdd(&hist[i & 7], 1);
    __syncthreads();

    float px = 0.5f * sgv;
    float py = -px * muv;
    float pw = 0.5f * wv;
    float pz = pw * ev;          // erev = +-1 on unmasked entries => pz = +-pw exactly

    if (nz) {
        const int r0 = slot & 7;
        const int myPr = ((i & 7) - r0) & 7;
        int start = 0;
#pragma unroll
        for (int b = 0; b < 8; b++)
            if ((((b - r0) & 7)) < myPr) start += hist[b];
        int rank = 0;
        for (int j = (i & 7); j < i; j += 8) rank += flag[j];
        int sl = start + rank;
        int p = sl >> 1, h = sl & 1;
        if (p < cap) {
            float* A = (float*)&TA[p * Nn + slot];
            A[h] = px; A[2 + h] = py;
            ((float*)&TBt[p * Nn + slot])[h] = pz;
            ((unsigned short*)&TI[p * Nn + slot])[h] = (unsigned short)(i * 16);
        }
    }

    redZ[i] = nz ? pz : 0.f;
    redW[i] = nz ? pw : 0.f;
    __syncthreads();
#pragma unroll
    for (int s = Nn / 2; s > 0; s >>= 1) {
        if (i < s) { redZ[i] += redZ[i + s]; redW[i] += redW[i + s]; }
        __syncthreads();
    }

    int tot = 0;
#pragma unroll
    for (int b = 0; b < 8; b++) tot += hist[b];
    const int wm = rc ? g_recCnt[slot] : g_senCnt[slot];
    const int myP = min((tot + 1) >> 1, cap);

    if (i == 0) {
        if (rc) { g_ncoT[0][slot] = redZ[0]; g_dcoT[0][slot] = redW[0]; }
        else    { g_ncoT[1][slot] = redZ[0]; g_dcoT[1][slot] = redW[0]; }
        if ((tot & 1) && (tot >> 1) < cap) {     // zero the stale odd half
            int p = tot >> 1;
            float* A = (float*)&TA[p * Nn + slot];  A[1] = 0.f; A[3] = 0.f;
            ((float*)&TBt[p * Nn + slot])[1] = 0.f;
            ((unsigned short*)&TI[p * Nn + slot])[1] = 0;
        }
    }
    for (int p = myP + i; p < wm; p += blockDim.x) {   // dummy pairs
        TA[p * Nn + slot]  = make_float4(0.f, 0.f, 0.f, 0.f);
        TBt[p * Nn + slot] = make_float2(0.f, 0.f);
        TI[p * Nn + slot]  = 0u;
    }
}

// ---------------------------------------------------------------------------
// Main kernel: lane t handles column g_perm[t]; TB=4 batches, 2 CTAs/SM.
// Transposed state vsT[Nn][4]; per-i gather = one LDS.128.
// ALL-f32 path; B table halved: pw recovered as |pz| (exact).
// ---------------------------------------------------------------------------

#define EVAL1(PXc, PYc, PZc, PWc, V, NUM, DEN)                               \
    {                                                                        \
        float tnh = fast_tanh(fmaf(PXc, V, PYc));                            \
        NUM = fmaf(PZc, tnh, NUM);                                           \
        DEN = fmaf(PWc, tnh, DEN);                                           \
    }

#define STEP(ID, PA, PB, VBASE, NUMA, DENA)                                  \
    {                                                                        \
        float4 va = *(const float4*)(VBASE + (ID & 0xFFFFu));                \
        float4 vb = *(const float4*)(VBASE + (ID >> 16));                    \
        float pwa = fabsf(PB.x), pwb = fabsf(PB.y);                          \
        EVAL1(PA.x, PA.z, PB.x, pwa, va.x, NUMA[0], DENA[0])                 \
        EVAL1(PA.y, PA.w, PB.y, pwb, vb.x, NUMA[0], DENA[0])                 \
        EVAL1(PA.x, PA.z, PB.x, pwa, va.y, NUMA[1], DENA[1])                 \
        EVAL1(PA.y, PA.w, PB.y, pwb, vb.y, NUMA[1], DENA[1])                 \
        EVAL1(PA.x, PA.z, PB.x, pwa, va.z, NUMA[2], DENA[2])                 \
        EVAL1(PA.y, PA.w, PB.y, pwb, vb.z, NUMA[2], DENA[2])                 \
        EVAL1(PA.x, PA.z, PB.x, pwa, va.w, NUMA[3], DENA[3])                 \
        EVAL1(PA.y, PA.w, PB.y, pwb, vb.w, NUMA[3], DENA[3])                 \
    }

// CNT is a multiple of 4 and >= 4 (warp-uniform). Copy-free rotated pipeline.
#define PASS(TA_, TB2_, TI_, CNT, VBASE, NUMA, DENA)                         \
    {                                                                        \
        unsigned i0_ = TI_[0 * Nn + t], i1_ = TI_[1 * Nn + t];               \
        float4 a0_ = TA_[0 * Nn + t], a1_ = TA_[1 * Nn + t];                 \
        float2 b0_ = TB2_[0 * Nn + t], b1_ = TB2_[1 * Nn + t];               \
        for (int k = 0; k < CNT; k += 4) {                                   \
            int k2 = k + 2;                                                  \
            unsigned i2_ = TI_[k2 * Nn + t], i3_ = TI_[(k2 + 1) * Nn + t];   \
            float4 a2_ = TA_[k2 * Nn + t], a3_ = TA_[(k2 + 1) * Nn + t];     \
            float2 b2_ = TB2_[k2 * Nn + t], b3_ = TB2_[(k2 + 1) * Nn + t];   \
            STEP(i0_, a0_, b0_, VBASE, NUMA, DENA)                           \
            STEP(i1_, a1_, b1_, VBASE, NUMA, DENA)                           \
            int k4 = (k + 4 < CNT) ? k + 4 : 0;                              \
            i0_ = TI_[k4 * Nn + t]; i1_ = TI_[(k4 + 1) * Nn + t];            \
            a0_ = TA_[k4 * Nn + t]; a1_ = TA_[(k4 + 1) * Nn + t];            \
            b0_ = TB2_[k4 * Nn + t]; b1_ = TB2_[(k4 + 1) * Nn + t];          \
            STEP(i2_, a2_, b2_, VBASE, NUMA, DENA)                           \
            STEP(i3_, a3_, b3_, VBASE, NUMA, DENA)                           \
        }                                                                    \
    }

__global__ void __launch_bounds__(256, 2)
ltc_kernel(const float* __restrict__ inputs,
           const float* __restrict__ states,
           const float* __restrict__ gleak,
           const float* __restrict__ vleak,
           const float* __restrict__ cm,
           const float* __restrict__ input_w,
           const float* __restrict__ input_b,
           const float* __restrict__ output_w,
           const float* __restrict__ output_b,
           float* __restrict__ out) {
    __shared__ __align__(16) float xsT[Ss][TB];
    __shared__ __align__(16) float vsT[Nn][TB];

    const int t  = threadIdx.x;
    const int n  = g_perm[t];                // column handled by this lane
    const int b0 = blockIdx.x * TB;

    for (int q = threadIdx.x; q < TB * Ss; q += 256) {
        int tb = q / Ss, s = q - tb * Ss;
        xsT[s][tb] = fmaf(inputs[(b0 + tb) * Ss + s], input_w[s], input_b[s]);
    }

    float vreg[TB];
#pragma unroll
    for (int tb = 0; tb < TB; tb++)
        vreg[tb] = states[(b0 + tb) * Nn + n];
    *(float4*)&vsT[n][0] = make_float4(vreg[0], vreg[1], vreg[2], vreg[3]);

    const float gl  = gleak[n];
    const float cmt = cm[n] * (float)NU;
    const float gv  = gl * vleak[n];
    const float nco = g_ncoT[0][t] + g_ncoT[1][t];
    const float dco = g_dcoT[0][t] + g_dcoT[1][t] + gl + cmt + 1e-8f;
    const int recCnt = g_recCnt[t];
    const int senCnt = g_senCnt[t];
    const char* xbase = (const char*)xsT;
    const char* vbase = (const char*)vsT;

    __syncthreads();

    // ---- sensory pass (variable part; once)
    float num[TB], den[TB];
#pragma unroll
    for (int tb = 0; tb < TB; tb++) { num[tb] = 0.f; den[tb] = 0.f; }
    PASS(g_senA, g_senB, g_senIdx, senCnt, xbase, num, den)

    float sn[TB], sd[TB];
#pragma unroll
    for (int tb = 0; tb < TB; tb++) {
        sn[tb] = num[tb] + nco;
        sd[tb] = den[tb] + dco;
    }

    // ---- 6 unfolds
    for (int u = 0; u < NU; u++) {
#pragma unroll
        for (int tb = 0; tb < TB; tb++) { num[tb] = sn[tb]; den[tb] = sd[tb]; }
        PASS(g_recA, g_recB, g_recIdx, recCnt, vbase, num, den)

        __syncthreads();   // all reads of vsT done
#pragma unroll
        for (int tb = 0; tb < TB; tb++) {
            float numerator = fmaf(cmt, vreg[tb], gv * num[tb]);
            vreg[tb] = __fdividef(numerator, den[tb]);
        }
        *(float4*)&vsT[n][0] = make_float4(vreg[0], vreg[1], vreg[2], vreg[3]);
        __syncthreads();   // new state visible
    }

    // ---- outputs: [B*M] motor outputs, then [B*N] final states
#pragma unroll
    for (int tb = 0; tb < TB; tb++) {
        int b = b0 + tb;
        out[Bb * Mm + b * Nn + n] = vreg[tb];
        if (n < Mm)
            out[b * Mm + n] = fmaf(vreg[tb], output_w[n], output_b[n]);
    }
}

// ---------------------------------------------------------------------------
extern "C" void kernel_launch(void* const* d_in, const int* in_sizes, int n_in,
                              void* d_out, int out_size) {
    const float* inputs   = (const float*)d_in[0];
    const float* states   = (const float*)d_in[1];
    const float* gleak    = (const float*)d_in[2];
    const float* vleak    = (const float*)d_in[3];
    const float* cm       = (const float*)d_in[4];
    const float* sigma    = (const float*)d_in[5];
    const float* mu       = (const float*)d_in[6];
    const float* w        = (const float*)d_in[7];
    const float* erev     = (const float*)d_in[8];
    const float* ssigma   = (const float*)d_in[9];
    const float* smu      = (const float*)d_in[10];
    const float* sw       = (const float*)d_in[11];
    const float* serev    = (const float*)d_in[12];
    const float* input_w  = (const float*)d_in[13];
    const float* input_b  = (const float*)d_in[14];
    const float* output_w = (const float*)d_in[15];
    const float* output_b = (const float*)d_in[16];
    const float* mask     = (const float*)d_in[17];
    const float* smask    = (const float*)d_in[18];
    float* out = (float*)d_out;

    dim3 pgrid(Nn, 2);
    pack_count<<<pgrid, 256>>>(mask, smask);
    pack_rank<<<1, 256>>>();
    pack_phase1<<<pgrid, 256>>>(sigma, mu, w, erev, mask,
                                ssigma, smu, sw, serev, smask);
    ltc_kernel<<<GRID, 256>>>(inputs, states, gleak, vleak, cm,
                              input_w, input_b, output_w, output_b, out);
}